// round 9
// baseline (speedup 1.0000x reference)
#include <cuda_runtime.h>

// FEDformer FourierBlock + out-projection + residual + series decomposition.
// R10 (= R7 re-bench; two infra timeouts): one block per NODE, looping over
// all 8 batch elements -> weight staging (Wq/Wo/W1/W2) and setup amortized
// 8x. Outer phases register-heavy: direct-LDG 3-mode DFT with register
// twiddle rotation, register xr, halo-only smem moving average.

#define NNODES 2000
#define LSEQ   96
#define DM     32
#define HH     4
#define EE     8
#define MM     3
#define KAVG   25
#define PAD    12
#define TPB    128

__global__ __launch_bounds__(TPB, 6) void feldm_kernel(
    const float* __restrict__ x,
    const float* __restrict__ Wq,
    const float* __restrict__ Wo,
    const float* __restrict__ bo,
    const float* __restrict__ W1,
    const float* __restrict__ W2,
    float* __restrict__ out,
    int B)
{
    const int tid  = threadIdx.x;
    const int w    = tid >> 5;
    const int lane = tid & 31;
    const int n    = blockIdx.x;

    __shared__ float sw1[HH*EE*EE*MM];              // 3 KB  per-node W1
    __shared__ float sw2[HH*EE*EE*MM];              // 3 KB  per-node W2
    __shared__ float sWq[DM*DM];                    // 4 KB
    __shared__ float sWo[DM*DM];                    // 4 KB
    __shared__ float spart[4*6*32];                 // 3 KB  DFT partials
    __shared__ float bAr[96], bAi[96];              // Xf, later Y
    __shared__ float bBr[96], bBi[96];              // X
    __shared__ float sPr[96], sPi[96];              // P
    __shared__ float sxr[LSEQ * DM];                // 12 KB xr (halo source)

    // ---- stage weights once per node (coalesced) ----
    {
        const float4* qg = (const float4*)Wq;
        const float4* og = (const float4*)Wo;
        float4* q4 = (float4*)sWq;  float4* o4 = (float4*)sWo;
        #pragma unroll
        for (int i = tid; i < (DM*DM)/4; i += TPB) { q4[i] = qg[i]; o4[i] = og[i]; }
        const float* w1g = W1 + (size_t)n * (HH*EE*EE*MM);
        const float* w2g = W2 + (size_t)n * (HH*EE*EE*MM);
        #pragma unroll
        for (int i = tid; i < HH*EE*EE*MM; i += TPB) { sw1[i] = w1g[i]; sw2[i] = w2g[i]; }
    }

    // rotation step constants: e^{i*2pi*mode/96}, modes {1,4,5}
    float pc1, ps1, pc4, ps4, pc5, ps5;
    sincospif(1.0f/48.0f, &ps1, &pc1);
    sincospif(4.0f/48.0f, &ps4, &pc4);
    sincospif(5.0f/48.0f, &ps5, &pc5);
    // start angles at t0 = 24w are multiples of pi/2 (modes 1,5: w*pi/2; mode 4: 0)
    const float c0 = (w == 0) ? 1.f : (w == 2 ? -1.f : 0.f);
    const float s0 = (w == 1) ? 1.f : (w == 3 ? -1.f : 0.f);
    const float bod = __ldg(bo + lane);

    const int t0 = w * 24;
    __syncthreads();     // weights staged

    for (int b = 0; b < B; ++b) {
        const size_t base = ((size_t)b * NNODES + n) * (size_t)(LSEQ * DM);
        const float* xg = x + base + (size_t)t0 * DM + lane;
        float r[24];                                // x, later xr

        // ---- forward 3-mode DFT over own t-range, direct LDG, x in regs ----
        {
            float c1 = c0, s1 = s0, c4 = 1.f, s4 = 0.f, c5 = c0, s5 = s0;
            float ar1=0.f, ai1=0.f, ar2=0.f, ai2=0.f, ar3=0.f, ai3=0.f;
            #pragma unroll
            for (int i = 0; i < 24; ++i) {
                const float v = xg[i * DM];
                r[i] = v;
                ar1 = fmaf(v, c1, ar1);  ai1 = fmaf(v, s1, ai1);
                ar2 = fmaf(v, c4, ar2);  ai2 = fmaf(v, s4, ai2);
                ar3 = fmaf(v, c5, ar3);  ai3 = fmaf(v, s5, ai3);
                float nc, ns;
                nc = fmaf(c1, pc1, -s1*ps1); ns = fmaf(s1, pc1, c1*ps1); c1 = nc; s1 = ns;
                nc = fmaf(c4, pc4, -s4*ps4); ns = fmaf(s4, pc4, c4*ps4); c4 = nc; s4 = ns;
                nc = fmaf(c5, pc5, -s5*ps5); ns = fmaf(s5, pc5, c5*ps5); c5 = nc; s5 = ns;
            }
            spart[(w*6 + 0)*32 + lane] = ar1;  spart[(w*6 + 1)*32 + lane] = ai1;
            spart[(w*6 + 2)*32 + lane] = ar2;  spart[(w*6 + 3)*32 + lane] = ai2;
            spart[(w*6 + 4)*32 + lane] = ar3;  spart[(w*6 + 5)*32 + lane] = ai3;
        }
        __syncthreads();

        // ---- mid phases (warp m < 3): reduce -> Wq -> node weights -> Wo ----
        if (w < 3) {
            const int m = w, j = lane;
            float fr = 0.f, fi = 0.f;
            #pragma unroll
            for (int ww = 0; ww < 4; ++ww) {
                fr += spart[(ww*6 + 2*m + 0)*32 + j];
                fi += spart[(ww*6 + 2*m + 1)*32 + j];
            }
            bAr[m*32 + j] = fr;
            bAi[m*32 + j] = -fi;                    // Xf = sum x*(cos - i sin)
            __syncwarp();
            // X = Xf @ Wq^T (rotated, conflict-free)
            float arr = 0.f, aii = 0.f;
            #pragma unroll 8
            for (int k = 0; k < 32; ++k) {
                const int dd = (j + k) & 31;
                const float wv = sWq[j*DM + dd];
                arr = fmaf(bAr[(m<<5) + dd], wv, arr);
                aii = fmaf(bAi[(m<<5) + dd], wv, aii);
            }
            bBr[m*32 + j] = arr;
            bBi[m*32 + j] = aii;
            __syncwarp();
            // Y[m][h][o] = sum_e X[m][h*8+e] * (W1 + i W2)[h][e][o][m]
            const int h = j >> 3, o = j & 7;
            float yr = 0.f, yi = 0.f;
            #pragma unroll
            for (int e = 0; e < EE; ++e) {
                const int wi = ((h*EE + e)*EE + o)*MM + m;
                const float w1v = sw1[wi], w2v = sw2[wi];
                const float xr = bBr[(m<<5) + (h<<3) + e];
                const float xi = bBi[(m<<5) + (h<<3) + e];
                yr = fmaf(xr, w1v, fmaf(-xi, w2v, yr));
                yi = fmaf(xr, w2v, fmaf( xi, w1v, yi));
            }
            __syncwarp();
            bAr[m*32 + j] = yr;
            bAi[m*32 + j] = yi;
            __syncwarp();
            // P = (2/L) * Y @ Wo^T (rotated)
            float pr = 0.f, pi = 0.f;
            #pragma unroll 8
            for (int k = 0; k < 32; ++k) {
                const int jj = (j + k) & 31;
                const float wv = sWo[j*DM + jj];
                pr = fmaf(bAr[(m<<5) + jj], wv, pr);
                pi = fmaf(bAi[(m<<5) + jj], wv, pi);
            }
            sPr[m*32 + j] = pr * (2.0f/(float)LSEQ);
            sPi[m*32 + j] = pi * (2.0f/(float)LSEQ);
        }
        __syncthreads();

        // ---- inverse 3-mode transform + residual into r[] (register xr) ----
        {
            const float Pr0 = sPr[     lane], Pi0 = sPi[     lane];
            const float Pr1 = sPr[32 + lane], Pi1 = sPi[32 + lane];
            const float Pr2 = sPr[64 + lane], Pi2 = sPi[64 + lane];
            float c1 = c0, s1 = s0, c4 = 1.f, s4 = 0.f, c5 = c0, s5 = s0;
            #pragma unroll
            for (int i = 0; i < 24; ++i) {
                float acc = bod;
                acc = fmaf(Pr0, c1, acc); acc = fmaf(-Pi0, s1, acc);
                acc = fmaf(Pr1, c4, acc); acc = fmaf(-Pi1, s4, acc);
                acc = fmaf(Pr2, c5, acc); acc = fmaf(-Pi2, s5, acc);
                r[i] += acc;
                sxr[(t0 + i)*DM + lane] = r[i];
                float nc, ns;
                nc = fmaf(c1, pc1, -s1*ps1); ns = fmaf(s1, pc1, c1*ps1); c1 = nc; s1 = ns;
                nc = fmaf(c4, pc4, -s4*ps4); ns = fmaf(s4, pc4, c4*ps4); c4 = nc; s4 = ns;
                nc = fmaf(c5, pc5, -s5*ps5); ns = fmaf(s5, pc5, c5*ps5); c5 = nc; s5 = ns;
            }
        }
        __syncthreads();

        // ---- sliding-window moving average; regs + smem halo ----
        {
            float win = 0.f;
            #pragma unroll
            for (int j = 0; j <= 12; ++j) win += r[j];
            if (w == 0) {
                win += 12.f * r[0];
            } else {
                #pragma unroll
                for (int j = 1; j <= 12; ++j) win += sxr[(t0 - j)*DM + lane];
            }
            float* og = out + base + (size_t)t0 * DM + lane;
            #pragma unroll
            for (int i = 0; i < 24; ++i) {
                og[i * DM] = r[i] - win * (1.0f/(float)KAVG);
                float vhi, vlo;
                if (i + 13 < 24)      vhi = r[i + 13];
                else if (w == 3)      vhi = r[23];
                else                  vhi = sxr[(t0 + i + 13)*DM + lane];
                if (i >= 12)          vlo = r[i - 12];
                else if (w == 0)      vlo = r[0];
                else                  vlo = sxr[(t0 + i - 12)*DM + lane];
                win += vhi - vlo;
            }
        }
        __syncthreads();    // protect sxr/spart before next batch iteration
    }
}

extern "C" void kernel_launch(void* const* d_in, const int* in_sizes, int n_in,
                              void* d_out, int out_size) {
    // metadata order: x, Wq, bq, Wk, bk, Wv, bv, Wo, bo, W1, W2
    const float* x  = (const float*)d_in[0];
    const float* Wq = (const float*)d_in[1];
    const float* Wo = (const float*)d_in[7];
    const float* bo = (const float*)d_in[8];
    const float* W1 = (const float*)d_in[9];
    const float* W2 = (const float*)d_in[10];
    float* out = (float*)d_out;

    const int B = in_sizes[0] / (NNODES * LSEQ * DM);
    feldm_kernel<<<NNODES, TPB>>>(x, Wq, Wo, bo, W1, W2, out, B);
}